// round 13
// baseline (speedup 1.0000x reference)
#include <cuda_runtime.h>
#include <cuda_fp16.h>
#include <math.h>

#define BB 16
#define HH 56
#define WW 56
#define CC 128
#define HW 3136
#define NELEM (BB*HW*CC)   // 6422528
#define CH 8               // channels per block
#define CST 3300           // padded per-channel SAT stride (floats); 3300 % 32 == 4
#define TMB 512            // threads per block
#define NBLK 256           // total blocks (16 cgroups x 16 batches); 256 <= 2*148 resident

// ---------------- device scratch (no allocation allowed) ----------------
__device__ uint4             g_t12h[NELEM/4];   // packed half2(t1,t2) per element
__device__ float             g_squeeze[BB*CC];
__device__ float             g_pmm[2*NBLK];     // per-block (min,max) partials
__device__ unsigned          g_count;           // barrier arrival counter (zero-init)
__device__ volatile unsigned g_gen;             // barrier generation (monotonic)

// sense-reversing grid barrier; replay-safe (gen monotonic, count self-resets)
__device__ __forceinline__ void grid_barrier(){
    __threadfence();
    __syncthreads();
    if (threadIdx.x == 0){
        unsigned gen = g_gen;
        unsigned arrived = atomicAdd(&g_count, 1) + 1;
        if (arrived == NBLK){
            g_count = 0;
            __threadfence();
            g_gen = gen + 1;
        } else {
            while (g_gen == gen) { }
        }
    }
    __syncthreads();
    __threadfence();
}

// ---------------- the single fused kernel ----------------
__global__ void __launch_bounds__(TMB, 2) k_fused(
    const float* __restrict__ x,     const float* __restrict__ kappa,
    const float* __restrict__ W1,    const float* __restrict__ b1,
    const float* __restrict__ W2,    const float* __restrict__ b2,
    const float* __restrict__ gamma, const float* __restrict__ beta,
    const float* __restrict__ bn_mean, const float* __restrict__ bn_var,
    float* __restrict__ out)
{
    extern __shared__ float sat[];      // CH * CST floats (105.6 KB)
    int b   = blockIdx.y;
    int c0  = blockIdx.x * CH;
    int bid = blockIdx.y * 16 + blockIdx.x;
    int t   = threadIdx.x;              // 512
    int ci  = t & 7;
    int c   = c0 + ci;

    __shared__ float s_bv[5];
    __shared__ float s_nbv;
    __shared__ float s_mm[2];
    __shared__ float smn[16], smx[16];
    __shared__ float red[16][8];
    __shared__ float s_hid[16];
    __shared__ float s_exc[CH];

    const float* xb = x + (size_t)b*HW*CC;

    // ---- phase 0: kappa constants (thread 0), raw slab load + min/max partial ----
    if (t == 0){
        const float LN2c = 0.6931471805599453f;
        float v[5]; float mean = 0.f;
        #pragma unroll
        for (int s = 0; s < 5; s++){
            float kk   = 1.f/(1.f + expf(-kappa[s]));
            float lk   = logf(kk + 1e-7f);
            float logk = 1.f/(1.f + expf(-lk));
            v[s] = logk + (float)(s+1)*LN2c;       // log_k + log_r
            mean += v[s];
        }
        mean *= 0.2f;
        float bv[5]; float bsum = 0.f;
        #pragma unroll
        for (int s = 0; s < 5; s++){ bv[s] = v[s]-mean; bsum += bv[s]; }
        bsum *= 0.2f;                               // force sum(bv) == 0 exactly
        float n2 = 0.f;
        #pragma unroll
        for (int s = 0; s < 5; s++){ bv[s] -= bsum; s_bv[s] = bv[s]; n2 += bv[s]*bv[s]; }
        s_nbv = sqrtf(n2);
    }

    float mn = 3.4e38f, mx = -3.4e38f;
    for (int idx = t; idx < HW*CH; idx += TMB){
        int cc = idx & 7; int p = idx >> 3;
        int h = p/56, w = p - h*56;
        float v = xb[p*CC + c0 + cc];
        sat[cc*CST + (h+1)*57 + (w+1)] = v;        // raw; normalized later in row prefix
        mn = fminf(mn, v); mx = fmaxf(mx, v);
    }
    #pragma unroll
    for (int o = 16; o; o >>= 1){
        mn = fminf(mn, __shfl_xor_sync(~0u, mn, o));
        mx = fmaxf(mx, __shfl_xor_sync(~0u, mx, o));
    }
    {
        int lane = t & 31, wp = t >> 5;
        if (lane == 0){ smn[wp] = mn; smx[wp] = mx; }
    }
    // zero SAT borders (row 0, col 0 of each 57x57 table); CH*57 = 456 < 512
    if (t < CH*57){
        int cc = t/57, j = t%57;
        sat[cc*CST + j]      = 0.f;     // row 0
        sat[cc*CST + j*57]   = 0.f;     // col 0
    }
    __syncthreads();
    if (t == 0){
        float a = smn[0], z = smx[0];
        #pragma unroll
        for (int i = 1; i < 16; i++){ a = fminf(a, smn[i]); z = fmaxf(z, smx[i]); }
        g_pmm[2*bid]   = a;
        g_pmm[2*bid+1] = z;
    }

    grid_barrier();   // ---- all partials visible ----

    // ---- phase 1: batch min/max, prefix sums (normalize fused), main loop ----
    if (t < 32){
        float mnv =  3.4e38f, mxv = -3.4e38f;
        if (t < 16){
            mnv = g_pmm[2*(b*16 + t)];
            mxv = g_pmm[2*(b*16 + t)+1];
        }
        #pragma unroll
        for (int o = 16; o; o >>= 1){
            mnv = fminf(mnv, __shfl_xor_sync(~0u, mnv, o));
            mxv = fmaxf(mxv, __shfl_xor_sync(~0u, mxv, o));
        }
        if (t == 0){ s_mm[0] = mnv; s_mm[1] = mxv; }
    }
    __syncthreads();
    float xmin = s_mm[0];
    float xmax = s_mm[1];
    float inv  = 1.f/(xmax - xmin + 1e-7f);

    // row prefix sums with fused normalization (448 rows, one per thread)
    if (t < 448){
        int cc = t/56; int i = (t%56) + 1;
        float* row = sat + cc*CST + i*57;
        float acc = 0.f;
        #pragma unroll
        for (int j = 1; j <= 56; j++){ acc += (row[j] - xmin) * inv; row[j] = acc; }
    }
    __syncthreads();

    // column prefix sums (448 cols, one per thread)
    if (t < 448){
        int cc = t/56; int j = (t%56) + 1;
        float* col = sat + cc*CST + j;
        float acc = 0.f;
        #pragma unroll
        for (int i = 1; i <= 56; i++){ acc += col[i*57]; col[i*57] = acc; }
    }
    __syncthreads();

    // per-thread constants
    float bns = gamma[c] * rsqrtf(bn_var[c] + 1e-3f);
    float bnb = beta[c] - bns*bn_mean[c];
    float bv0 = s_bv[0], bv1 = s_bv[1], bv2 = s_bv[2], bv3 = s_bv[3], bv4 = s_bv[4];
    const float LN2 = 0.69314718055994531f;
    float C1  = LN2 * s_nbv;            // multiplies |alpha|*sqrt(na2)
    float C1sq = C1 * C1;
    const float* S = sat + ci*CST;
    __half2* t12p = ((__half2*)g_t12h) + (size_t)b*HW*CC;

    float asum = 0.f;
    int p0 = t >> 3;                   // 0..63, pixel stride 64 per iter
    const int KK[5] = {2,4,8,16,32};
    const int PB[5] = {0,1,3,7,15};    // TF SAME pad_before = (k-1)/2

    for (int it = 0; it < 49; it++){
        int p = p0 + it*64;
        int h = p/56, w = p - h*56;
        float L[5];   // log2(m + eps)  -- MUFU LG2, everything stays in log2 basis
        #pragma unroll
        for (int s = 0; s < 5; s++){
            int r0 = max(h - PB[s], 0), r1 = min(h - PB[s] + KK[s], 56);
            int q0 = max(w - PB[s], 0), q1 = min(w - PB[s] + KK[s], 56);
            float m = S[r1*57 + q1] - S[r0*57 + q1] - S[r1*57 + q0] + S[r0*57 + q0];
            L[s] = __log2f(m + 1e-7f);
        }
        float sumL = (L[0]+L[1]) + (L[2]+L[3]) + L[4];
        // alpha (natural-log OLS slope) == 0.1*(2(L4-L0)+(L3-L1)) in log2 basis
        float alpha = 0.1f * (2.f*(L[4]-L[0]) + (L[3]-L[1]));
        // dot(a,bv) = sum(L*bv) since sum(bv)==0 ;  |a|^2 = sum(L^2) - (sum L)^2/5
        float dotv = L[0]*bv0 + L[1]*bv1 + L[2]*bv2 + L[3]*bv3 + L[4]*bv4;
        float sq   = L[0]*L[0] + L[1]*L[1] + L[2]*L[2] + L[3]*L[3] + L[4]*L[4];
        float na2  = fmaxf(fmaf(-0.2f*sumL, sumL, sq), 0.f);
        // cos = LN2*alpha*dotv / (sqrt(na2)*|alpha|*C1 + eps)  ~=  N * rsqrt(na2*alpha^2*C1^2 + eps^2)
        float a2   = alpha * alpha;
        float cosv = (LN2 * alpha * dotv) * rsqrtf(fmaf(na2 * a2, C1sq, 1e-14f));
        float sim  = fmaf(cosv, 0.5f, 0.5f);
        float sg   = __fdividef(1.f, 1.f + __expf(-fmaf(bns, alpha, bnb)));
        float xs   = (__ldg(&xb[p*CC + c]) - xmin) * inv;   // L1/L2-hit re-read
        t12p[p*CC + c] = __floats2half2_rn(sim * sg, (1.f - sim) * xs);
        asum += alpha;
    }

    // per-channel alpha sum -> squeeze (block owns full H*W of its 8 channels)
    asum += __shfl_xor_sync(~0u, asum, 8);
    asum += __shfl_xor_sync(~0u, asum, 16);
    {
        int lane = t & 31, wp = t >> 5;
        if (lane < 8) red[wp][lane] = asum;
    }
    __syncthreads();
    if (t < 8){
        float s = 0.f;
        #pragma unroll
        for (int i = 0; i < 16; i++) s += red[i][t];
        g_squeeze[b*CC + c0 + t] = s * (1.f/3136.f);
    }

    grid_barrier();   // ---- all squeeze + t12 visible ----

    // ---- phase 2: SE-MLP (per block) + blend own slab ----
    // hidden[j]: 16 warps, warp w computes hidden[w]; each lane sums 4 channels
    {
        int wp = t >> 5, lane = t & 31;
        float acc = 0.f;
        #pragma unroll
        for (int k = 0; k < 4; k++){
            int cc = lane + 32*k;
            acc += g_squeeze[b*CC + cc] * __ldg(&W1[cc*16 + wp]);
        }
        #pragma unroll
        for (int o = 16; o; o >>= 1) acc += __shfl_xor_sync(~0u, acc, o);
        if (lane == 0) s_hid[wp] = fmaxf(acc + __ldg(&b1[wp]), 0.f);
    }
    __syncthreads();
    if (t < CH){
        float a = __ldg(&b2[c0 + t]);
        #pragma unroll
        for (int j = 0; j < 16; j++) a += s_hid[j] * __ldg(&W2[j*CC + c0 + t]);
        s_exc[t] = __fdividef(1.f, 1.f + __expf(-a));
    }
    __syncthreads();

    // blend: uint4 = 4 x half2 (4 channels), vectorized; slab = HW * (CH/4) quads
    {
        float e0 = s_exc[0], e1 = s_exc[1], e2 = s_exc[2], e3 = s_exc[3];
        float e4 = s_exc[4], e5 = s_exc[5], e6 = s_exc[6], e7 = s_exc[7];
        const uint4* t4 = (const uint4*)(((const __half2*)g_t12h) + (size_t)b*HW*CC);
        float4* o4 = (float4*)(out + (size_t)b*HW*CC);
        const int NQ = HW * (CH/4);     // 6272 quads per block slab
        for (int idx = t; idx < NQ; idx += TMB){
            int q = idx & 1; int p = idx >> 1;          // q: which 4-channel quad
            int gi = p*(CC/4) + (c0 >> 2) + q;          // global quad index
            uint4 u = t4[gi];
            float2 f0 = __half22float2(*(__half2*)&u.x);
            float2 f1 = __half22float2(*(__half2*)&u.y);
            float2 f2 = __half22float2(*(__half2*)&u.z);
            float2 f3 = __half22float2(*(__half2*)&u.w);
            float4 o;
            if (q == 0){
                o.x = fmaf(f0.y, e0, f0.x);
                o.y = fmaf(f1.y, e1, f1.x);
                o.z = fmaf(f2.y, e2, f2.x);
                o.w = fmaf(f3.y, e3, f3.x);
            } else {
                o.x = fmaf(f0.y, e4, f0.x);
                o.y = fmaf(f1.y, e5, f1.x);
                o.z = fmaf(f2.y, e6, f2.x);
                o.w = fmaf(f3.y, e7, f3.x);
            }
            o4[gi] = o;
        }
    }
}

// ---------------- launch ----------------
extern "C" void kernel_launch(void* const* d_in, const int* in_sizes, int n_in,
                              void* d_out, int out_size)
{
    const float* x       = (const float*)d_in[0];
    const float* kappa   = (const float*)d_in[1];
    const float* W1      = (const float*)d_in[2];
    const float* b1      = (const float*)d_in[3];
    const float* W2      = (const float*)d_in[4];
    const float* b2      = (const float*)d_in[5];
    const float* gamma   = (const float*)d_in[6];
    const float* beta    = (const float*)d_in[7];
    const float* bn_mean = (const float*)d_in[8];
    const float* bn_var  = (const float*)d_in[9];

    cudaFuncSetAttribute(k_fused, cudaFuncAttributeMaxDynamicSharedMemorySize, CH*CST*4);

    dim3 gb(CC/CH, BB);   // (16, 16) = 256 blocks, all co-resident at 2/SM
    k_fused<<<gb, TMB, CH*CST*4>>>(x, kappa, W1, b1, W2, b2,
                                   gamma, beta, bn_mean, bn_var, (float*)d_out);
}

// round 14
// speedup vs baseline: 1.0517x; 1.0517x over previous
#include <cuda_runtime.h>
#include <cuda_fp16.h>
#include <math.h>

#define BB 16
#define HH 56
#define WW 56
#define CC 128
#define HW 3136
#define NELEM (BB*HW*CC)   // 6422528
#define CH 8               // channels per block
#define CST 3300           // padded per-channel SAT stride (floats); 3300 % 32 == 4
#define TMB 448            // threads per block = 56 pixel groups x 8 channels
#define BPB 16             // blocks per batch (channel groups)

// ---------------- device scratch (no allocation allowed) ----------------
__device__ uint4             g_t12h[NELEM/4];   // packed half2(t1,t2) per element
__device__ float             g_squeeze[BB*CC];
__device__ float             g_pmm[2*BB*BPB];   // per-block (min,max) partials
__device__ unsigned          g_count[BB*32];    // per-batch arrival counters (padded)
__device__ volatile unsigned g_gen[BB*32];      // per-batch generations (monotonic)

// per-batch sense-reversing barrier (16 blocks); replay-safe (gen monotonic)
__device__ __forceinline__ void batch_barrier(int b){
    __threadfence();
    __syncthreads();
    if (threadIdx.x == 0){
        unsigned* cnt = &g_count[b*32];
        volatile unsigned* gen = &g_gen[b*32];
        unsigned g = *gen;
        unsigned arrived = atomicAdd(cnt, 1) + 1;
        if (arrived == BPB){
            *cnt = 0;
            __threadfence();
            *gen = g + 1;
        } else {
            while (*gen == g) { }
        }
    }
    __syncthreads();
    __threadfence();
}

// ---------------- the single fused kernel ----------------
__global__ void __launch_bounds__(TMB, 2) k_fused(
    const float* __restrict__ x,     const float* __restrict__ kappa,
    const float* __restrict__ W1,    const float* __restrict__ b1,
    const float* __restrict__ W2,    const float* __restrict__ b2,
    const float* __restrict__ gamma, const float* __restrict__ beta,
    const float* __restrict__ bn_mean, const float* __restrict__ bn_var,
    float* __restrict__ out)
{
    extern __shared__ float sat[];      // CH * CST floats (105.6 KB)
    int b   = blockIdx.y;
    int c0  = blockIdx.x * CH;
    int bid = b * BPB + blockIdx.x;
    int t   = threadIdx.x;              // 448
    int ci  = t & 7;
    int c   = c0 + ci;

    __shared__ float s_bv[5];
    __shared__ float s_nbv;
    __shared__ float s_mm[2];
    __shared__ float smn[TMB/32], smx[TMB/32];
    __shared__ float red[TMB/32][8];
    __shared__ float s_hid[16];
    __shared__ float s_exc[CH];

    const float* xb = x + (size_t)b*HW*CC;

    // ---- phase 0: kappa constants (thread 0), raw slab load + min/max partial ----
    if (t == 0){
        const float LN2c = 0.6931471805599453f;
        float v[5]; float mean = 0.f;
        #pragma unroll
        for (int s = 0; s < 5; s++){
            float kk   = 1.f/(1.f + expf(-kappa[s]));
            float lk   = logf(kk + 1e-7f);
            float logk = 1.f/(1.f + expf(-lk));
            v[s] = logk + (float)(s+1)*LN2c;       // log_k + log_r
            mean += v[s];
        }
        mean *= 0.2f;
        float bv[5]; float bsum = 0.f;
        #pragma unroll
        for (int s = 0; s < 5; s++){ bv[s] = v[s]-mean; bsum += bv[s]; }
        bsum *= 0.2f;                               // force sum(bv) == 0 exactly
        float n2 = 0.f;
        #pragma unroll
        for (int s = 0; s < 5; s++){ bv[s] -= bsum; s_bv[s] = bv[s]; n2 += bv[s]*bv[s]; }
        s_nbv = sqrtf(n2);
    }

    float mn = 3.4e38f, mx = -3.4e38f;
    for (int idx = t; idx < HW*CH; idx += TMB){     // 56 exact iterations
        int cc = idx & 7; int p = idx >> 3;
        int h = p/56, w = p - h*56;
        float v = xb[p*CC + c0 + cc];
        sat[cc*CST + (h+1)*57 + (w+1)] = v;        // raw; normalized later in row prefix
        mn = fminf(mn, v); mx = fmaxf(mx, v);
    }
    #pragma unroll
    for (int o = 16; o; o >>= 1){
        mn = fminf(mn, __shfl_xor_sync(~0u, mn, o));
        mx = fmaxf(mx, __shfl_xor_sync(~0u, mx, o));
    }
    {
        int lane = t & 31, wp = t >> 5;
        if (lane == 0){ smn[wp] = mn; smx[wp] = mx; }
    }
    // zero SAT borders (row 0, col 0 of each 57x57 table); CH*57 = 456 > 448
    for (int i = t; i < CH*57; i += TMB){
        int cc = i/57, j = i%57;
        sat[cc*CST + j]      = 0.f;     // row 0
        sat[cc*CST + j*57]   = 0.f;     // col 0
    }
    __syncthreads();
    if (t == 0){
        float a = smn[0], z = smx[0];
        #pragma unroll
        for (int i = 1; i < TMB/32; i++){ a = fminf(a, smn[i]); z = fmaxf(z, smx[i]); }
        g_pmm[2*bid]   = a;
        g_pmm[2*bid+1] = z;
    }

    batch_barrier(b);   // ---- same-batch partials visible ----

    // ---- phase 1: batch min/max, prefix sums (normalize fused), main loop ----
    if (t < 32){
        float mnv =  3.4e38f, mxv = -3.4e38f;
        if (t < BPB){
            mnv = g_pmm[2*(b*BPB + t)];
            mxv = g_pmm[2*(b*BPB + t)+1];
        }
        #pragma unroll
        for (int o = 16; o; o >>= 1){
            mnv = fminf(mnv, __shfl_xor_sync(~0u, mnv, o));
            mxv = fmaxf(mxv, __shfl_xor_sync(~0u, mxv, o));
        }
        if (t == 0){ s_mm[0] = mnv; s_mm[1] = mxv; }
    }
    __syncthreads();
    float xmin = s_mm[0];
    float xmax = s_mm[1];
    float inv  = 1.f/(xmax - xmin + 1e-7f);

    // row prefix sums with fused normalization (448 rows = 448 threads)
    {
        int cc = t/56; int i = (t%56) + 1;
        float* row = sat + cc*CST + i*57;
        float acc = 0.f;
        #pragma unroll
        for (int j = 1; j <= 56; j++){ acc += (row[j] - xmin) * inv; row[j] = acc; }
    }
    __syncthreads();

    // column prefix sums (448 cols = 448 threads)
    {
        int cc = t/56; int j = (t%56) + 1;
        float* col = sat + cc*CST + j;
        float acc = 0.f;
        #pragma unroll
        for (int i = 1; i <= 56; i++){ acc += col[i*57]; col[i*57] = acc; }
    }
    __syncthreads();

    // per-thread constants
    float bns = gamma[c] * rsqrtf(bn_var[c] + 1e-3f);
    float bnb = beta[c] - bns*bn_mean[c];
    float bv0 = s_bv[0], bv1 = s_bv[1], bv2 = s_bv[2], bv3 = s_bv[3], bv4 = s_bv[4];
    const float LN2 = 0.69314718055994531f;
    float C1   = LN2 * s_nbv;
    float C1sq = C1 * C1;
    const float* S = sat + ci*CST;
    __half2* t12p = ((__half2*)g_t12h) + (size_t)b*HW*CC;

    const int KK[5] = {2,4,8,16,32};
    const int PB[5] = {0,1,3,7,15};    // TF SAME pad_before = (k-1)/2

    // column-major mapping: thread owns column w0 = t>>3, sweeps h = 0..55.
    // -> column clamps are loop-invariant registers; row clamps warp-uniform.
    int w0 = t >> 3;                   // 0..55
    int q0r[5], q1r[5];
    #pragma unroll
    for (int s = 0; s < 5; s++){
        q0r[s] = max(w0 - PB[s], 0);
        q1r[s] = min(w0 - PB[s] + KK[s], 56);
    }

    float asum = 0.f;
    for (int h = 0; h < 56; h++){
        int p = h*56 + w0;
        float L[5];   // log2(m + eps)  -- MUFU LG2, log2 basis throughout
        #pragma unroll
        for (int s = 0; s < 5; s++){
            int r0 = max(h - PB[s], 0) * 57;              // uniform across warp
            int r1 = min(h - PB[s] + KK[s], 56) * 57;     // uniform across warp
            float m = S[r1 + q1r[s]] - S[r0 + q1r[s]] - S[r1 + q0r[s]] + S[r0 + q0r[s]];
            L[s] = __log2f(m + 1e-7f);
        }
        float sumL = (L[0]+L[1]) + (L[2]+L[3]) + L[4];
        float alpha = 0.1f * (2.f*(L[4]-L[0]) + (L[3]-L[1]));
        float dotv = L[0]*bv0 + L[1]*bv1 + L[2]*bv2 + L[3]*bv3 + L[4]*bv4;
        float sq   = L[0]*L[0] + L[1]*L[1] + L[2]*L[2] + L[3]*L[3] + L[4]*L[4];
        float na2  = fmaxf(fmaf(-0.2f*sumL, sumL, sq), 0.f);
        float a2   = alpha * alpha;
        float cosv = (LN2 * alpha * dotv) * rsqrtf(fmaf(na2 * a2, C1sq, 1e-14f));
        float sim  = fmaf(cosv, 0.5f, 0.5f);
        float sg   = __fdividef(1.f, 1.f + __expf(-fmaf(bns, alpha, bnb)));
        float xs   = (__ldg(&xb[p*CC + c]) - xmin) * inv;   // L2-hit re-read
        t12p[p*CC + c] = __floats2half2_rn(sim * sg, (1.f - sim) * xs);
        asum += alpha;
    }

    // per-channel alpha sum -> squeeze (block owns full H*W of its 8 channels)
    asum += __shfl_xor_sync(~0u, asum, 8);
    asum += __shfl_xor_sync(~0u, asum, 16);
    {
        int lane = t & 31, wp = t >> 5;
        if (lane < 8) red[wp][lane] = asum;
    }
    __syncthreads();
    if (t < 8){
        float s = 0.f;
        #pragma unroll
        for (int i = 0; i < TMB/32; i++) s += red[i][t];
        g_squeeze[b*CC + c0 + t] = s * (1.f/3136.f);
    }

    batch_barrier(b);   // ---- same-batch squeeze visible ----

    // ---- phase 2: SE-MLP (per block) + blend own slab ----
    // hidden[j] = relu(b1[j] + sum_c sq[c]*W1[c*16+j]); threads t<256 = (j<16) x (cl<16)
    if (t < 256){
        int j = t >> 4, cl = t & 15;
        float acc = 0.f;
        #pragma unroll
        for (int k = 0; k < 8; k++){
            int cc = cl + 16*k;
            acc += g_squeeze[b*CC + cc] * __ldg(&W1[cc*16 + j]);
        }
        #pragma unroll
        for (int o = 8; o; o >>= 1) acc += __shfl_xor_sync(~0u, acc, o);
        if (cl == 0) s_hid[j] = fmaxf(acc + __ldg(&b1[j]), 0.f);
    }
    __syncthreads();
    if (t < CH){
        float a = __ldg(&b2[c0 + t]);
        #pragma unroll
        for (int j = 0; j < 16; j++) a += s_hid[j] * __ldg(&W2[j*CC + c0 + t]);
        s_exc[t] = __fdividef(1.f, 1.f + __expf(-a));
    }
    __syncthreads();

    // blend: uint4 = 4 x half2 (4 channels); slab = HW * 2 quads, 14 exact iters
    {
        float e0 = s_exc[0], e1 = s_exc[1], e2 = s_exc[2], e3 = s_exc[3];
        float e4 = s_exc[4], e5 = s_exc[5], e6 = s_exc[6], e7 = s_exc[7];
        const uint4* t4 = (const uint4*)(((const __half2*)g_t12h) + (size_t)b*HW*CC);
        float4* o4 = (float4*)(out + (size_t)b*HW*CC);
        const int NQ = HW * (CH/4);     // 6272 quads per block slab
        for (int idx = t; idx < NQ; idx += TMB){
            int q = idx & 1; int p = idx >> 1;
            int gi = p*(CC/4) + (c0 >> 2) + q;
            uint4 u = t4[gi];
            float2 f0 = __half22float2(*(__half2*)&u.x);
            float2 f1 = __half22float2(*(__half2*)&u.y);
            float2 f2 = __half22float2(*(__half2*)&u.z);
            float2 f3 = __half22float2(*(__half2*)&u.w);
            float4 o;
            if (q == 0){
                o.x = fmaf(f0.y, e0, f0.x);
                o.y = fmaf(f1.y, e1, f1.x);
                o.z = fmaf(f2.y, e2, f2.x);
                o.w = fmaf(f3.y, e3, f3.x);
            } else {
                o.x = fmaf(f0.y, e4, f0.x);
                o.y = fmaf(f1.y, e5, f1.x);
                o.z = fmaf(f2.y, e6, f2.x);
                o.w = fmaf(f3.y, e7, f3.x);
            }
            o4[gi] = o;
        }
    }
}

// ---------------- launch ----------------
extern "C" void kernel_launch(void* const* d_in, const int* in_sizes, int n_in,
                              void* d_out, int out_size)
{
    const float* x       = (const float*)d_in[0];
    const float* kappa   = (const float*)d_in[1];
    const float* W1      = (const float*)d_in[2];
    const float* b1      = (const float*)d_in[3];
    const float* W2      = (const float*)d_in[4];
    const float* b2      = (const float*)d_in[5];
    const float* gamma   = (const float*)d_in[6];
    const float* beta    = (const float*)d_in[7];
    const float* bn_mean = (const float*)d_in[8];
    const float* bn_var  = (const float*)d_in[9];

    cudaFuncSetAttribute(k_fused, cudaFuncAttributeMaxDynamicSharedMemorySize, CH*CST*4);

    dim3 gb(CC/CH, BB);   // (16, 16) = 256 blocks, all co-resident at 2/SM
    k_fused<<<gb, TMB, CH*CST*4>>>(x, kappa, W1, b1, W2, b2,
                                   gamma, beta, bn_mean, bn_var, (float*)d_out);
}

// round 16
// speedup vs baseline: 1.0868x; 1.0333x over previous
#include <cuda_runtime.h>
#include <cuda_fp16.h>
#include <math.h>

#define BB 16
#define HH 56
#define WW 56
#define CC 128
#define HW 3136
#define NELEM (BB*HW*CC)   // 6422528
#define CH 8               // channels per block
#define CST 3300           // padded per-channel SAT stride (floats); 3300 % 32 == 4
#define TMB 448            // threads per block = 56 pixel groups x 8 channels
#define BPB 16             // blocks per batch (channel groups)

// ---------------- device scratch (no allocation allowed) ----------------
__device__ uint4             g_t12h[NELEM/4];   // packed half2(t1,t2) per element
__device__ float             g_squeeze[BB*CC];
__device__ float             g_pmm[2*BB*BPB];   // per-block (min,max) partials
__device__ unsigned          g_count[BB*32];    // per-batch arrival counters (padded)
__device__ volatile unsigned g_gen[BB*32];      // per-batch generations (monotonic)

// per-batch sense-reversing barrier (16 blocks); replay-safe (gen monotonic)
__device__ __forceinline__ void batch_barrier(int b){
    __threadfence();
    __syncthreads();
    if (threadIdx.x == 0){
        unsigned* cnt = &g_count[b*32];
        volatile unsigned* gen = &g_gen[b*32];
        unsigned g = *gen;
        unsigned arrived = atomicAdd(cnt, 1) + 1;
        if (arrived == BPB){
            *cnt = 0;
            __threadfence();
            *gen = g + 1;
        } else {
            while (*gen == g) { }
        }
    }
    __syncthreads();
    __threadfence();
}

// ---------------- the single fused kernel ----------------
__global__ void __launch_bounds__(TMB, 2) k_fused(
    const float* __restrict__ x,     const float* __restrict__ kappa,
    const float* __restrict__ W1,    const float* __restrict__ b1,
    const float* __restrict__ W2,    const float* __restrict__ b2,
    const float* __restrict__ gamma, const float* __restrict__ beta,
    const float* __restrict__ bn_mean, const float* __restrict__ bn_var,
    float* __restrict__ out)
{
    extern __shared__ float sat[];      // CH * CST floats (105.6 KB)
    int b   = blockIdx.y;
    int c0  = blockIdx.x * CH;
    int bid = b * BPB + blockIdx.x;
    int t   = threadIdx.x;              // 448
    int ci  = t & 7;
    int c   = c0 + ci;

    __shared__ float s_bv[5];
    __shared__ float s_nbv;
    __shared__ float s_mm[2];
    __shared__ float smn[TMB/32], smx[TMB/32];
    __shared__ float red[TMB/32][8];
    __shared__ float s_hid[16];
    __shared__ float s_exc[CH];

    const float* xb = x + (size_t)b*HW*CC;

    // ---- phase 0: kappa constants (thread 0), raw slab load + min/max partial ----
    if (t == 0){
        const float LN2c = 0.6931471805599453f;
        float v[5]; float mean = 0.f;
        #pragma unroll
        for (int s = 0; s < 5; s++){
            float kk   = 1.f/(1.f + expf(-kappa[s]));
            float lk   = logf(kk + 1e-7f);
            float logk = 1.f/(1.f + expf(-lk));
            v[s] = logk + (float)(s+1)*LN2c;       // log_k + log_r
            mean += v[s];
        }
        mean *= 0.2f;
        float bv[5]; float bsum = 0.f;
        #pragma unroll
        for (int s = 0; s < 5; s++){ bv[s] = v[s]-mean; bsum += bv[s]; }
        bsum *= 0.2f;                               // force sum(bv) == 0 exactly
        float n2 = 0.f;
        #pragma unroll
        for (int s = 0; s < 5; s++){ bv[s] -= bsum; s_bv[s] = bv[s]; n2 += bv[s]*bv[s]; }
        s_nbv = sqrtf(n2);
    }

    float mn = 3.4e38f, mx = -3.4e38f;
    for (int idx = t; idx < HW*CH; idx += TMB){     // 56 exact iterations
        int cc = idx & 7; int p = idx >> 3;
        int h = p/56, w = p - h*56;
        float v = xb[p*CC + c0 + cc];
        sat[cc*CST + (h+1)*57 + (w+1)] = v;        // raw; normalized later in row prefix
        mn = fminf(mn, v); mx = fmaxf(mx, v);
    }
    #pragma unroll
    for (int o = 16; o; o >>= 1){
        mn = fminf(mn, __shfl_xor_sync(~0u, mn, o));
        mx = fmaxf(mx, __shfl_xor_sync(~0u, mx, o));
    }
    {
        int lane = t & 31, wp = t >> 5;
        if (lane == 0){ smn[wp] = mn; smx[wp] = mx; }
    }
    // zero SAT borders (row 0, col 0 of each 57x57 table); CH*57 = 456 > 448
    for (int i = t; i < CH*57; i += TMB){
        int cc = i/57, j = i%57;
        sat[cc*CST + j]      = 0.f;     // row 0
        sat[cc*CST + j*57]   = 0.f;     // col 0
    }
    __syncthreads();
    if (t == 0){
        float a = smn[0], z = smx[0];
        #pragma unroll
        for (int i = 1; i < TMB/32; i++){ a = fminf(a, smn[i]); z = fmaxf(z, smx[i]); }
        g_pmm[2*bid]   = a;
        g_pmm[2*bid+1] = z;
    }

    batch_barrier(b);   // ---- same-batch partials visible ----

    // ---- phase 1: batch min/max, prefix sums (normalize fused), main loop ----
    if (t < 32){
        float mnv =  3.4e38f, mxv = -3.4e38f;
        if (t < BPB){
            mnv = g_pmm[2*(b*BPB + t)];
            mxv = g_pmm[2*(b*BPB + t)+1];
        }
        #pragma unroll
        for (int o = 16; o; o >>= 1){
            mnv = fminf(mnv, __shfl_xor_sync(~0u, mnv, o));
            mxv = fmaxf(mxv, __shfl_xor_sync(~0u, mxv, o));
        }
        if (t == 0){ s_mm[0] = mnv; s_mm[1] = mxv; }
    }
    __syncthreads();
    float xmin = s_mm[0];
    float xmax = s_mm[1];
    float inv  = 1.f/(xmax - xmin + 1e-7f);

    // row prefix sums with fused normalization (448 rows = 448 threads)
    {
        int cc = t/56; int i = (t%56) + 1;
        float* row = sat + cc*CST + i*57;
        float acc = 0.f;
        #pragma unroll
        for (int j = 1; j <= 56; j++){ acc += (row[j] - xmin) * inv; row[j] = acc; }
    }
    __syncthreads();

    // column prefix sums (448 cols = 448 threads)
    {
        int cc = t/56; int j = (t%56) + 1;
        float* col = sat + cc*CST + j;
        float acc = 0.f;
        #pragma unroll
        for (int i = 1; i <= 56; i++){ acc += col[i*57]; col[i*57] = acc; }
    }
    __syncthreads();

    // per-thread constants
    float bns = gamma[c] * rsqrtf(bn_var[c] + 1e-3f);
    float bnb = beta[c] - bns*bn_mean[c];
    float bv0 = s_bv[0], bv1 = s_bv[1], bv2 = s_bv[2], bv3 = s_bv[3], bv4 = s_bv[4];
    const float LN2 = 0.69314718055994531f;
    float C1   = LN2 * s_nbv;
    float C1sq = C1 * C1;
    const float* S = sat + ci*CST;
    __half2* t12p = ((__half2*)g_t12h) + (size_t)b*HW*CC;

    const int KK[5] = {2,4,8,16,32};
    const int PB[5] = {0,1,3,7,15};    // TF SAME pad_before = (k-1)/2

    // column-major mapping: thread owns column w0 = t>>3, sweeps h = 0..55.
    // -> column clamps are loop-invariant registers; row clamps warp-uniform.
    int w0 = t >> 3;                   // 0..55
    int q0r[5], q1r[5];
    #pragma unroll
    for (int s = 0; s < 5; s++){
        q0r[s] = max(w0 - PB[s], 0);
        q1r[s] = min(w0 - PB[s] + KK[s], 56);
    }

    float asum = 0.f;
    #pragma unroll 2
    for (int h = 0; h < 56; h++){
        int p = h*56 + w0;
        float L[5];   // log2(m + eps)  -- MUFU LG2, log2 basis throughout
        #pragma unroll
        for (int s = 0; s < 5; s++){
            int r0 = max(h - PB[s], 0) * 57;              // uniform across warp
            int r1 = min(h - PB[s] + KK[s], 56) * 57;     // uniform across warp
            float m = S[r1 + q1r[s]] - S[r0 + q1r[s]] - S[r1 + q0r[s]] + S[r0 + q0r[s]];
            L[s] = __log2f(m + 1e-7f);
        }
        // xs from the SAT 1x1 cell (exact; replaces global reload of x)
        int rc0 = h*57, rc1 = rc0 + 57;
        float xs = (S[rc1 + w0+1] - S[rc0 + w0+1]) - (S[rc1 + w0] - S[rc0 + w0]);

        float sumL = (L[0]+L[1]) + (L[2]+L[3]) + L[4];
        float alpha = 0.1f * (2.f*(L[4]-L[0]) + (L[3]-L[1]));
        float dotv = L[0]*bv0 + L[1]*bv1 + L[2]*bv2 + L[3]*bv3 + L[4]*bv4;
        float sq   = L[0]*L[0] + L[1]*L[1] + L[2]*L[2] + L[3]*L[3] + L[4]*L[4];
        float na2  = fmaxf(fmaf(-0.2f*sumL, sumL, sq), 0.f);
        float a2   = alpha * alpha;
        float cosv = (LN2 * alpha * dotv) * rsqrtf(fmaf(na2 * a2, C1sq, 1e-14f));
        float sim  = fmaf(cosv, 0.5f, 0.5f);
        float sg   = __fdividef(1.f, 1.f + __expf(-fmaf(bns, alpha, bnb)));
        t12p[p*CC + c] = __floats2half2_rn(sim * sg, (1.f - sim) * xs);
        asum += alpha;
    }

    // per-channel alpha sum -> squeeze (block owns full H*W of its 8 channels)
    asum += __shfl_xor_sync(~0u, asum, 8);
    asum += __shfl_xor_sync(~0u, asum, 16);
    {
        int lane = t & 31, wp = t >> 5;
        if (lane < 8) red[wp][lane] = asum;
    }
    __syncthreads();
    if (t < 8){
        float s = 0.f;
        #pragma unroll
        for (int i = 0; i < TMB/32; i++) s += red[i][t];
        g_squeeze[b*CC + c0 + t] = s * (1.f/3136.f);
    }

    batch_barrier(b);   // ---- same-batch squeeze visible ----

    // ---- phase 2: SE-MLP (per block) + blend own slab ----
    // hidden[j] = relu(b1[j] + sum_c sq[c]*W1[c*16+j]); threads t<256 = (j<16) x (cl<16)
    if (t < 256){
        int j = t >> 4, cl = t & 15;
        float acc = 0.f;
        #pragma unroll
        for (int k = 0; k < 8; k++){
            int cc = cl + 16*k;
            acc += g_squeeze[b*CC + cc] * __ldg(&W1[cc*16 + j]);
        }
        #pragma unroll
        for (int o = 8; o; o >>= 1) acc += __shfl_xor_sync(~0u, acc, o);
        if (cl == 0) s_hid[j] = fmaxf(acc + __ldg(&b1[j]), 0.f);
    }
    __syncthreads();
    if (t < CH){
        float a = __ldg(&b2[c0 + t]);
        #pragma unroll
        for (int j = 0; j < 16; j++) a += s_hid[j] * __ldg(&W2[j*CC + c0 + t]);
        s_exc[t] = __fdividef(1.f, 1.f + __expf(-a));
    }
    __syncthreads();

    // blend: uint4 = 4 x half2 (4 channels); slab = HW * 2 quads, 14 exact iters
    {
        float e0 = s_exc[0], e1 = s_exc[1], e2 = s_exc[2], e3 = s_exc[3];
        float e4 = s_exc[4], e5 = s_exc[5], e6 = s_exc[6], e7 = s_exc[7];
        const uint4* t4 = (const uint4*)(((const __half2*)g_t12h) + (size_t)b*HW*CC);
        float4* o4 = (float4*)(out + (size_t)b*HW*CC);
        const int NQ = HW * (CH/4);     // 6272 quads per block slab
        for (int idx = t; idx < NQ; idx += TMB){
            int q = idx & 1; int p = idx >> 1;
            int gi = p*(CC/4) + (c0 >> 2) + q;
            uint4 u = t4[gi];
            float2 f0 = __half22float2(*(__half2*)&u.x);
            float2 f1 = __half22float2(*(__half2*)&u.y);
            float2 f2 = __half22float2(*(__half2*)&u.z);
            float2 f3 = __half22float2(*(__half2*)&u.w);
            float4 o;
            if (q == 0){
                o.x = fmaf(f0.y, e0, f0.x);
                o.y = fmaf(f1.y, e1, f1.x);
                o.z = fmaf(f2.y, e2, f2.x);
                o.w = fmaf(f3.y, e3, f3.x);
            } else {
                o.x = fmaf(f0.y, e4, f0.x);
                o.y = fmaf(f1.y, e5, f1.x);
                o.z = fmaf(f2.y, e6, f2.x);
                o.w = fmaf(f3.y, e7, f3.x);
            }
            o4[gi] = o;
        }
    }
}

// ---------------- launch ----------------
extern "C" void kernel_launch(void* const* d_in, const int* in_sizes, int n_in,
                              void* d_out, int out_size)
{
    const float* x       = (const float*)d_in[0];
    const float* kappa   = (const float*)d_in[1];
    const float* W1      = (const float*)d_in[2];
    const float* b1      = (const float*)d_in[3];
    const float* W2      = (const float*)d_in[4];
    const float* b2      = (const float*)d_in[5];
    const float* gamma   = (const float*)d_in[6];
    const float* beta    = (const float*)d_in[7];
    const float* bn_mean = (const float*)d_in[8];
    const float* bn_var  = (const float*)d_in[9];

    cudaFuncSetAttribute(k_fused, cudaFuncAttributeMaxDynamicSharedMemorySize, CH*CST*4);

    dim3 gb(CC/CH, BB);   // (16, 16) = 256 blocks, all co-resident at 2/SM
    k_fused<<<gb, TMB, CH*CST*4>>>(x, kappa, W1, b1, W2, b2,
                                   gamma, beta, bn_mean, bn_var, (float*)d_out);
}